// round 1
// baseline (speedup 1.0000x reference)
#include <cuda_runtime.h>
#include <math.h>

#define BB 8
#define N1 8192
#define N2 2048
#define C1 128
#define C2 256
#define KIN1 384
#define O1 256
#define O2 128
#define BN_EPS 1e-5f
#define MIN_DIST 1e-10f
#define P_TOTAL (BB * N1)   // 65536 samples per channel for BN stats

// ---------------- scratch (no allocations allowed) ----------------
__device__ float g_p2T[BB * N2 * C2];        // points2 transposed [B][N2][C2]
__device__ int   g_knn_idx[BB * N1 * 3];
__device__ float g_knn_w[BB * N1 * 3];
__device__ float g_interp[BB * C2 * N1];     // interpolated feats [B][C2][N1]
__device__ float g_y1[BB * O1 * N1];         // conv1 pre-BN
__device__ float g_y2[BB * O2 * N1];         // conv2 pre-BN
__device__ float g_sum0[O1], g_sq0[O1], g_sum1[O2], g_sq1[O2];
__device__ float g_scale0[O1], g_shift0[O1], g_scale1[O2], g_shift1[O2];

// ---------------- zero stats each launch (graph replays!) ----------------
__global__ void init_stats_kernel() {
    int t = threadIdx.x;
    if (t < O1) { g_sum0[t] = 0.f; g_sq0[t] = 0.f; }
    if (t < O2) { g_sum1[t] = 0.f; g_sq1[t] = 0.f; }
}

// ---------------- transpose points2 [B,C2,N2] -> [B,N2,C2] ----------------
__global__ void transpose_p2_kernel(const float* __restrict__ p2) {
    __shared__ float tile[32][33];
    int b  = blockIdx.z;
    int c0 = blockIdx.y * 32;
    int n0 = blockIdx.x * 32;
    int tx = threadIdx.x, ty = threadIdx.y;
    #pragma unroll
    for (int i = ty; i < 32; i += 8)
        tile[i][tx] = p2[(size_t)b * C2 * N2 + (size_t)(c0 + i) * N2 + n0 + tx];
    __syncthreads();
    #pragma unroll
    for (int i = ty; i < 32; i += 8)
        g_p2T[(size_t)b * N2 * C2 + (size_t)(n0 + i) * C2 + c0 + tx] = tile[tx][i];
}

// ---------------- 3-NN (squared-dist order == dist order) ----------------
__global__ __launch_bounds__(128) void knn_kernel(const float* __restrict__ xyz1,
                                                  const float* __restrict__ xyz2) {
    __shared__ float4 s_p[N2];   // 32 KB: (x,y,z,|p|^2)
    int b  = blockIdx.x >> 6;            // N1/128 = 64 tiles per batch
    int n0 = (blockIdx.x & 63) << 7;
    const float* x2 = xyz2 + (size_t)b * N2 * 3;
    for (int j = threadIdx.x; j < N2; j += 128) {
        float px = x2[j * 3], py = x2[j * 3 + 1], pz = x2[j * 3 + 2];
        s_p[j] = make_float4(px, py, pz, px * px + py * py + pz * pz);
    }
    __syncthreads();

    int n = n0 + threadIdx.x;
    const float* q = xyz1 + ((size_t)b * N1 + n) * 3;
    float qx = q[0], qy = q[1], qz = q[2];
    float qn = qx * qx + qy * qy + qz * qz;

    float d0 = 3.4e38f, d1 = 3.4e38f, d2 = 3.4e38f;
    int   i0 = 0, i1 = 0, i2 = 0;

    #pragma unroll 4
    for (int j = 0; j < N2; j++) {
        float4 p = s_p[j];
        float t  = fmaf(qx, p.x, fmaf(qy, p.y, qz * p.z));
        float sq = qn + p.w - 2.f * t;
        if (sq < d2) {
            if (sq < d1) {
                d2 = d1; i2 = i1;
                if (sq < d0) { d1 = d0; i1 = i0; d0 = sq; i0 = j; }
                else         { d1 = sq; i1 = j; }
            } else { d2 = sq; i2 = j; }
        }
    }
    float e0 = fmaxf(sqrtf(fmaxf(d0, 0.f)), MIN_DIST);
    float e1 = fmaxf(sqrtf(fmaxf(d1, 0.f)), MIN_DIST);
    float e2 = fmaxf(sqrtf(fmaxf(d2, 0.f)), MIN_DIST);
    float w0 = 1.f / e0, w1 = 1.f / e1, w2 = 1.f / e2;
    float inv = 1.f / (w0 + w1 + w2);
    size_t on = ((size_t)b * N1 + n) * 3;
    g_knn_idx[on] = i0; g_knn_idx[on + 1] = i1; g_knn_idx[on + 2] = i2;
    g_knn_w[on] = w0 * inv; g_knn_w[on + 1] = w1 * inv; g_knn_w[on + 2] = w2 * inv;
}

// ---------------- interpolation: gather contiguous rows from p2T ----------------
// block = 256 threads (one per channel), 32 query points per block
__global__ __launch_bounds__(256) void interp_kernel() {
    __shared__ int   s_idx[32 * 3];
    __shared__ float s_w[32 * 3];
    __shared__ float s_out[32 * 257];   // [p][c] padded (stride 257) -> conflict-free both phases
    int b  = blockIdx.x >> 8;           // N1/32 = 256 tiles per batch
    int n0 = (blockIdx.x & 255) << 5;
    int t  = threadIdx.x;
    if (t < 96) {
        size_t base = ((size_t)b * N1 + n0) * 3 + t;
        s_idx[t] = g_knn_idx[base];
        s_w[t]   = g_knn_w[base];
    }
    __syncthreads();

    int c = t;   // 0..255
    #pragma unroll 4
    for (int p = 0; p < 32; p++) {
        int k = p * 3;
        const float* r0 = g_p2T + ((size_t)b * N2 + s_idx[k + 0]) * C2 + c;
        const float* r1 = g_p2T + ((size_t)b * N2 + s_idx[k + 1]) * C2 + c;
        const float* r2 = g_p2T + ((size_t)b * N2 + s_idx[k + 2]) * C2 + c;
        s_out[p * 257 + c] = fmaf(s_w[k], *r0, fmaf(s_w[k + 1], *r1, s_w[k + 2] * (*r2)));
    }
    __syncthreads();
    // write [c][n] coalesced (32 consecutive floats per channel row)
    for (int e = t; e < 32 * 256; e += 256) {
        int cc = e >> 5, pp = e & 31;
        g_interp[((size_t)b * C2 + cc) * N1 + n0 + pp] = s_out[pp * 257 + cc];
    }
}

// ---------------- fused conv (+input BN-ReLU for layer 1) + stats ----------------
// 128x128 tile, KC=8, 256 threads, 8x8 per thread.
template <int LAYER>
__global__ __launch_bounds__(256) void conv_kernel(const float* __restrict__ xin,
                                                   const float* __restrict__ wgt,
                                                   const float* __restrict__ bias) {
    constexpr int O = (LAYER == 0) ? O1 : O2;
    constexpr int K = (LAYER == 0) ? KIN1 : O1;

    __shared__ __align__(16) float sA[8][132];  // [k][o]
    __shared__ __align__(16) float sB[8][132];  // [k][n]
    __shared__ float s_sum[128], s_sq[128];

    int tid = threadIdx.x;
    int tx = tid & 15, ty = tid >> 4;
    int b  = blockIdx.x >> 6;
    int n0 = (blockIdx.x & 63) << 7;
    int o0 = blockIdx.y << 7;

    if (tid < 128) { s_sum[tid] = 0.f; s_sq[tid] = 0.f; }

    float acc[8][8];
    #pragma unroll
    for (int i = 0; i < 8; i++)
        #pragma unroll
        for (int j = 0; j < 8; j++) acc[i][j] = 0.f;

    int aw_o = tid >> 1;          // 0..127
    int aw_k = (tid & 1) * 4;     // 0 / 4
    int bl_k = tid >> 5;          // 0..7
    int bl_n = (tid & 31) * 4;    // 0..124

    for (int kk = 0; kk < K; kk += 8) {
        float4 wa = *(const float4*)(wgt + (size_t)(o0 + aw_o) * K + kk + aw_k);

        int c = kk + bl_k;
        const float* src;
        if (LAYER == 0)
            src = (c < C1) ? (xin + ((size_t)b * C1 + c) * N1)
                           : (g_interp + ((size_t)b * C2 + (c - C1)) * N1);
        else
            src = g_y1 + ((size_t)b * O1 + c) * N1;
        float4 xb = *(const float4*)(src + n0 + bl_n);
        if (LAYER == 1) {  // apply BN0 + ReLU on the fly
            float sc = g_scale0[c], sh = g_shift0[c];
            xb.x = fmaxf(fmaf(xb.x, sc, sh), 0.f);
            xb.y = fmaxf(fmaf(xb.y, sc, sh), 0.f);
            xb.z = fmaxf(fmaf(xb.z, sc, sh), 0.f);
            xb.w = fmaxf(fmaf(xb.w, sc, sh), 0.f);
        }
        __syncthreads();   // previous tile fully consumed
        sA[aw_k + 0][aw_o] = wa.x;
        sA[aw_k + 1][aw_o] = wa.y;
        sA[aw_k + 2][aw_o] = wa.z;
        sA[aw_k + 3][aw_o] = wa.w;
        *(float4*)&sB[bl_k][bl_n] = xb;
        __syncthreads();

        #pragma unroll
        for (int k = 0; k < 8; k++) {
            float a[8], bb[8];
            *(float4*)(a)      = *(const float4*)&sA[k][ty * 8];
            *(float4*)(a + 4)  = *(const float4*)&sA[k][ty * 8 + 4];
            *(float4*)(bb)     = *(const float4*)&sB[k][tx * 8];
            *(float4*)(bb + 4) = *(const float4*)&sB[k][tx * 8 + 4];
            #pragma unroll
            for (int i = 0; i < 8; i++)
                #pragma unroll
                for (int j = 0; j < 8; j++)
                    acc[i][j] = fmaf(a[i], bb[j], acc[i][j]);
        }
    }

    // epilogue: bias, store, per-channel stats (shuffle-reduced over the 16 tx lanes)
    float* ybuf = (LAYER == 0) ? g_y1 : g_y2;
    #pragma unroll
    for (int i = 0; i < 8; i++) {
        int o = ty * 8 + i;
        float bi = bias[o0 + o];
        float vout[8];
        float s = 0.f, s2 = 0.f;
        #pragma unroll
        for (int j = 0; j < 8; j++) {
            float v = acc[i][j] + bi;
            vout[j] = v;
            s += v;
            s2 = fmaf(v, v, s2);
        }
        float* dst = ybuf + ((size_t)b * O + o0 + o) * N1 + n0 + tx * 8;
        *(float4*)dst       = *(float4*)vout;
        *(float4*)(dst + 4) = *(float4*)(vout + 4);
        #pragma unroll
        for (int off = 8; off; off >>= 1) {
            s  += __shfl_down_sync(0xffffffff, s,  off, 16);
            s2 += __shfl_down_sync(0xffffffff, s2, off, 16);
        }
        if (tx == 0) { atomicAdd(&s_sum[o], s); atomicAdd(&s_sq[o], s2); }
    }
    __syncthreads();
    if (tid < 128) {
        float* gs = (LAYER == 0) ? g_sum0 : g_sum1;
        float* gq = (LAYER == 0) ? g_sq0  : g_sq1;
        atomicAdd(&gs[o0 + tid], s_sum[tid]);
        atomicAdd(&gq[o0 + tid], s_sq[tid]);
    }
}

// ---------------- BN finalize: scale/shift per channel ----------------
template <int LAYER>
__global__ void bn_finalize_kernel(const float* __restrict__ gamma,
                                   const float* __restrict__ beta) {
    constexpr int O = (LAYER == 0) ? O1 : O2;
    int o = threadIdx.x;
    if (o < O) {
        const float inv = 1.0f / (float)P_TOTAL;
        float su = (LAYER == 0) ? g_sum0[o] : g_sum1[o];
        float sq = (LAYER == 0) ? g_sq0[o]  : g_sq1[o];
        float mu  = su * inv;
        float var = sq * inv - mu * mu;
        float sc  = gamma[o] * rsqrtf(var + BN_EPS);
        if (LAYER == 0) { g_scale0[o] = sc; g_shift0[o] = beta[o] - mu * sc; }
        else            { g_scale1[o] = sc; g_shift1[o] = beta[o] - mu * sc; }
    }
}

// ---------------- final BN1 + ReLU -> output ----------------
__global__ __launch_bounds__(256) void final_kernel(float* __restrict__ out) {
    int i = blockIdx.x * blockDim.x + threadIdx.x;    // float4 index
    float4 v = ((const float4*)g_y2)[i];
    int c = ((i * 4) / N1) & (O2 - 1);
    float sc = g_scale1[c], sh = g_shift1[c];
    v.x = fmaxf(fmaf(v.x, sc, sh), 0.f);
    v.y = fmaxf(fmaf(v.y, sc, sh), 0.f);
    v.z = fmaxf(fmaf(v.z, sc, sh), 0.f);
    v.w = fmaxf(fmaf(v.w, sc, sh), 0.f);
    ((float4*)out)[i] = v;
}

// ---------------- launch ----------------
extern "C" void kernel_launch(void* const* d_in, const int* in_sizes, int n_in,
                              void* d_out, int out_size) {
    const float* xyz1    = (const float*)d_in[0];
    const float* xyz2    = (const float*)d_in[1];
    const float* points1 = (const float*)d_in[2];
    const float* points2 = (const float*)d_in[3];
    const float* w0  = (const float*)d_in[4];
    const float* b0  = (const float*)d_in[5];
    const float* ga0 = (const float*)d_in[6];
    const float* be0 = (const float*)d_in[7];
    const float* w1  = (const float*)d_in[8];
    const float* b1  = (const float*)d_in[9];
    const float* ga1 = (const float*)d_in[10];
    const float* be1 = (const float*)d_in[11];
    float* out = (float*)d_out;

    init_stats_kernel<<<1, 256>>>();
    transpose_p2_kernel<<<dim3(N2 / 32, C2 / 32, BB), dim3(32, 8)>>>(points2);
    knn_kernel<<<BB * (N1 / 128), 128>>>(xyz1, xyz2);
    interp_kernel<<<BB * (N1 / 32), 256>>>();
    conv_kernel<0><<<dim3(BB * (N1 / 128), O1 / 128), 256>>>(points1, w0, b0);
    bn_finalize_kernel<0><<<1, 256>>>(ga0, be0);
    conv_kernel<1><<<dim3(BB * (N1 / 128), O2 / 128), 256>>>(nullptr, w1, b1);
    bn_finalize_kernel<1><<<1, 128>>>(ga1, be1);
    final_kernel<<<(BB * O2 * N1 / 4) / 256, 256>>>(out);
}

// round 2
// speedup vs baseline: 1.0730x; 1.0730x over previous
#include <cuda_runtime.h>
#include <math.h>

#define BB 8
#define N1 8192
#define N2 2048
#define C1 128
#define C2 256
#define KIN1 384
#define O1 256
#define O2 128
#define BN_EPS 1e-5f
#define MIN_DIST 1e-10f
#define P_TOTAL (BB * N1)   // 65536 samples per channel for BN stats

// ---------------- scratch (no allocations allowed) ----------------
__device__ float g_p2T[BB * N2 * C2];        // points2 transposed [B][N2][C2]
__device__ int   g_knn_idx[BB * N1 * 3];
__device__ float g_knn_w[BB * N1 * 3];
__device__ float g_interp[BB * C2 * N1];     // interpolated feats [B][C2][N1]
__device__ float g_y1[BB * O1 * N1];         // conv1 pre-BN
__device__ float g_y2[BB * O2 * N1];         // conv2 pre-BN
__device__ float g_sum0[O1], g_sq0[O1], g_sum1[O2], g_sq1[O2];
__device__ float g_scale0[O1], g_shift0[O1], g_scale1[O2], g_shift1[O2];

// ---------------- zero stats each launch (graph replays!) ----------------
__global__ void init_stats_kernel() {
    int t = threadIdx.x;
    if (t < O1) { g_sum0[t] = 0.f; g_sq0[t] = 0.f; }
    if (t < O2) { g_sum1[t] = 0.f; g_sq1[t] = 0.f; }
}

// ---------------- transpose points2 [B,C2,N2] -> [B,N2,C2] ----------------
__global__ void transpose_p2_kernel(const float* __restrict__ p2) {
    __shared__ float tile[32][33];
    int b  = blockIdx.z;
    int c0 = blockIdx.y * 32;
    int n0 = blockIdx.x * 32;
    int tx = threadIdx.x, ty = threadIdx.y;
    #pragma unroll
    for (int i = ty; i < 32; i += 8)
        tile[i][tx] = p2[(size_t)b * C2 * N2 + (size_t)(c0 + i) * N2 + n0 + tx];
    __syncthreads();
    #pragma unroll
    for (int i = ty; i < 32; i += 8)
        g_p2T[(size_t)b * N2 * C2 + (size_t)(n0 + i) * C2 + c0 + tx] = tile[tx][i];
}

// ---------------- 3-NN (squared-dist order == dist order) ----------------
__global__ __launch_bounds__(128) void knn_kernel(const float* __restrict__ xyz1,
                                                  const float* __restrict__ xyz2) {
    __shared__ float4 s_p[N2];   // 32 KB: (x,y,z,|p|^2)
    int b  = blockIdx.x >> 6;            // N1/128 = 64 tiles per batch
    int n0 = (blockIdx.x & 63) << 7;
    const float* x2 = xyz2 + (size_t)b * N2 * 3;
    for (int j = threadIdx.x; j < N2; j += 128) {
        float px = x2[j * 3], py = x2[j * 3 + 1], pz = x2[j * 3 + 2];
        s_p[j] = make_float4(px, py, pz, px * px + py * py + pz * pz);
    }
    __syncthreads();

    int n = n0 + threadIdx.x;
    const float* q = xyz1 + ((size_t)b * N1 + n) * 3;
    float qx = q[0], qy = q[1], qz = q[2];
    float qn = qx * qx + qy * qy + qz * qz;

    float d0 = 3.4e38f, d1 = 3.4e38f, d2 = 3.4e38f;
    int   i0 = 0, i1 = 0, i2 = 0;

    #pragma unroll 4
    for (int j = 0; j < N2; j++) {
        float4 p = s_p[j];
        float t  = fmaf(qx, p.x, fmaf(qy, p.y, qz * p.z));
        float sq = qn + p.w - 2.f * t;
        if (sq < d2) {
            if (sq < d1) {
                d2 = d1; i2 = i1;
                if (sq < d0) { d1 = d0; i1 = i0; d0 = sq; i0 = j; }
                else         { d1 = sq; i1 = j; }
            } else { d2 = sq; i2 = j; }
        }
    }
    float e0 = fmaxf(sqrtf(fmaxf(d0, 0.f)), MIN_DIST);
    float e1 = fmaxf(sqrtf(fmaxf(d1, 0.f)), MIN_DIST);
    float e2 = fmaxf(sqrtf(fmaxf(d2, 0.f)), MIN_DIST);
    float w0 = 1.f / e0, w1 = 1.f / e1, w2 = 1.f / e2;
    float inv = 1.f / (w0 + w1 + w2);
    size_t on = ((size_t)b * N1 + n) * 3;
    g_knn_idx[on] = i0; g_knn_idx[on + 1] = i1; g_knn_idx[on + 2] = i2;
    g_knn_w[on] = w0 * inv; g_knn_w[on + 1] = w1 * inv; g_knn_w[on + 2] = w2 * inv;
}

// ---------------- interpolation: gather contiguous rows from p2T ----------------
__global__ __launch_bounds__(256) void interp_kernel() {
    __shared__ int   s_idx[32 * 3];
    __shared__ float s_w[32 * 3];
    __shared__ float s_out[32 * 257];   // [p][c] padded -> conflict-free both phases
    int b  = blockIdx.x >> 8;           // N1/32 = 256 tiles per batch
    int n0 = (blockIdx.x & 255) << 5;
    int t  = threadIdx.x;
    if (t < 96) {
        size_t base = ((size_t)b * N1 + n0) * 3 + t;
        s_idx[t] = g_knn_idx[base];
        s_w[t]   = g_knn_w[base];
    }
    __syncthreads();

    int c = t;   // 0..255
    #pragma unroll 8
    for (int p = 0; p < 32; p++) {
        int k = p * 3;
        const float* r0 = g_p2T + ((size_t)b * N2 + s_idx[k + 0]) * C2 + c;
        const float* r1 = g_p2T + ((size_t)b * N2 + s_idx[k + 1]) * C2 + c;
        const float* r2 = g_p2T + ((size_t)b * N2 + s_idx[k + 2]) * C2 + c;
        s_out[p * 257 + c] = fmaf(s_w[k], *r0, fmaf(s_w[k + 1], *r1, s_w[k + 2] * (*r2)));
    }
    __syncthreads();
    for (int e = t; e < 32 * 256; e += 256) {
        int cc = e >> 5, pp = e & 31;
        g_interp[((size_t)b * C2 + cc) * N1 + n0 + pp] = s_out[pp * 257 + cc];
    }
}

// ---------------- fused conv (+input BN-ReLU for layer 1) + stats ----------------
// 128x128 tile, KC=8, 256 threads, 8x8 per thread, packed f32x2 FMA inner loop.
template <int LAYER>
__global__ __launch_bounds__(256) void conv_kernel(const float* __restrict__ xin,
                                                   const float* __restrict__ wgt,
                                                   const float* __restrict__ bias) {
    constexpr int O = (LAYER == 0) ? O1 : O2;
    constexpr int K = (LAYER == 0) ? KIN1 : O1;

    __shared__ __align__(16) float sA[8][132];  // [k][o]  (row = 528 B, 16B-aligned)
    __shared__ __align__(16) float sB[8][132];  // [k][n]
    __shared__ float s_sum[128], s_sq[128];

    int tid = threadIdx.x;
    int tx = tid & 15, ty = tid >> 4;
    int b  = blockIdx.x >> 6;
    int n0 = (blockIdx.x & 63) << 7;
    int o0 = blockIdx.y << 7;

    if (tid < 128) { s_sum[tid] = 0.f; s_sq[tid] = 0.f; }

    // packed accumulators: acc2[i][j] holds columns (2j, 2j+1) of row i
    unsigned long long acc2[8][4];
    #pragma unroll
    for (int i = 0; i < 8; i++)
        #pragma unroll
        for (int j = 0; j < 4; j++) acc2[i][j] = 0ull;

    unsigned sB_addr = (unsigned)__cvta_generic_to_shared(&sB[0][0]);

    int aw_o = tid >> 1;          // 0..127
    int aw_k = (tid & 1) * 4;     // 0 / 4
    int bl_k = tid >> 5;          // 0..7
    int bl_n = (tid & 31) * 4;    // 0..124

    for (int kk = 0; kk < K; kk += 8) {
        float4 wa = *(const float4*)(wgt + (size_t)(o0 + aw_o) * K + kk + aw_k);

        int c = kk + bl_k;
        const float* src;
        if (LAYER == 0)
            src = (c < C1) ? (xin + ((size_t)b * C1 + c) * N1)
                           : (g_interp + ((size_t)b * C2 + (c - C1)) * N1);
        else
            src = g_y1 + ((size_t)b * O1 + c) * N1;
        float4 xb = *(const float4*)(src + n0 + bl_n);
        if (LAYER == 1) {  // apply BN0 + ReLU on the fly
            float sc = g_scale0[c], sh = g_shift0[c];
            xb.x = fmaxf(fmaf(xb.x, sc, sh), 0.f);
            xb.y = fmaxf(fmaf(xb.y, sc, sh), 0.f);
            xb.z = fmaxf(fmaf(xb.z, sc, sh), 0.f);
            xb.w = fmaxf(fmaf(xb.w, sc, sh), 0.f);
        }
        __syncthreads();   // previous tile fully consumed
        sA[aw_k + 0][aw_o] = wa.x;
        sA[aw_k + 1][aw_o] = wa.y;
        sA[aw_k + 2][aw_o] = wa.z;
        sA[aw_k + 3][aw_o] = wa.w;
        *(float4*)&sB[bl_k][bl_n] = xb;
        __syncthreads();

        #pragma unroll
        for (int k = 0; k < 8; k++) {
            float a[8];
            *(float4*)(a)     = *(const float4*)&sA[k][ty * 8];
            *(float4*)(a + 4) = *(const float4*)&sA[k][ty * 8 + 4];
            unsigned long long ap[8];
            #pragma unroll
            for (int i = 0; i < 8; i++) {
                unsigned ai = __float_as_uint(a[i]);
                asm("mov.b64 %0, {%1, %1};" : "=l"(ap[i]) : "r"(ai));
            }
            unsigned long long bq[4];
            unsigned addr = sB_addr + (unsigned)(k * 528 + tx * 32);
            asm volatile("ld.shared.v2.b64 {%0, %1}, [%2];"
                         : "=l"(bq[0]), "=l"(bq[1]) : "r"(addr));
            asm volatile("ld.shared.v2.b64 {%0, %1}, [%2];"
                         : "=l"(bq[2]), "=l"(bq[3]) : "r"(addr + 16));
            #pragma unroll
            for (int i = 0; i < 8; i++)
                #pragma unroll
                for (int j = 0; j < 4; j++)
                    asm("fma.rn.f32x2 %0, %1, %2, %0;"
                        : "+l"(acc2[i][j]) : "l"(ap[i]), "l"(bq[j]));
        }
    }

    // epilogue: bias, store, per-channel stats (shuffle-reduced over the 16 tx lanes)
    float* ybuf = (LAYER == 0) ? g_y1 : g_y2;
    #pragma unroll
    for (int i = 0; i < 8; i++) {
        int o = ty * 8 + i;
        float bi = bias[o0 + o];
        float vout[8];
        float s = 0.f, s2 = 0.f;
        #pragma unroll
        for (int j = 0; j < 4; j++) {
            unsigned ulo, uhi;
            asm("mov.b64 {%0, %1}, %2;" : "=r"(ulo), "=r"(uhi) : "l"(acc2[i][j]));
            float vlo = __uint_as_float(ulo) + bi;
            float vhi = __uint_as_float(uhi) + bi;
            vout[2 * j]     = vlo;
            vout[2 * j + 1] = vhi;
            s += vlo + vhi;
            s2 = fmaf(vlo, vlo, s2);
            s2 = fmaf(vhi, vhi, s2);
        }
        float* dst = ybuf + ((size_t)b * O + o0 + o) * N1 + n0 + tx * 8;
        *(float4*)dst       = *(float4*)vout;
        *(float4*)(dst + 4) = *(float4*)(vout + 4);
        #pragma unroll
        for (int off = 8; off; off >>= 1) {
            s  += __shfl_down_sync(0xffffffff, s,  off, 16);
            s2 += __shfl_down_sync(0xffffffff, s2, off, 16);
        }
        if (tx == 0) { atomicAdd(&s_sum[o], s); atomicAdd(&s_sq[o], s2); }
    }
    __syncthreads();
    if (tid < 128) {
        float* gs = (LAYER == 0) ? g_sum0 : g_sum1;
        float* gq = (LAYER == 0) ? g_sq0  : g_sq1;
        atomicAdd(&gs[o0 + tid], s_sum[tid]);
        atomicAdd(&gq[o0 + tid], s_sq[tid]);
    }
}

// ---------------- BN finalize: scale/shift per channel ----------------
template <int LAYER>
__global__ void bn_finalize_kernel(const float* __restrict__ gamma,
                                   const float* __restrict__ beta) {
    constexpr int O = (LAYER == 0) ? O1 : O2;
    int o = threadIdx.x;
    if (o < O) {
        const float inv = 1.0f / (float)P_TOTAL;
        float su = (LAYER == 0) ? g_sum0[o] : g_sum1[o];
        float sq = (LAYER == 0) ? g_sq0[o]  : g_sq1[o];
        float mu  = su * inv;
        float var = sq * inv - mu * mu;
        float sc  = gamma[o] * rsqrtf(var + BN_EPS);
        if (LAYER == 0) { g_scale0[o] = sc; g_shift0[o] = beta[o] - mu * sc; }
        else            { g_scale1[o] = sc; g_shift1[o] = beta[o] - mu * sc; }
    }
}

// ---------------- final BN1 + ReLU -> output ----------------
__global__ __launch_bounds__(256) void final_kernel(float* __restrict__ out) {
    int i = blockIdx.x * blockDim.x + threadIdx.x;    // float4 index
    float4 v = ((const float4*)g_y2)[i];
    int c = ((i * 4) / N1) & (O2 - 1);
    float sc = g_scale1[c], sh = g_shift1[c];
    v.x = fmaxf(fmaf(v.x, sc, sh), 0.f);
    v.y = fmaxf(fmaf(v.y, sc, sh), 0.f);
    v.z = fmaxf(fmaf(v.z, sc, sh), 0.f);
    v.w = fmaxf(fmaf(v.w, sc, sh), 0.f);
    ((float4*)out)[i] = v;
}

// ---------------- launch ----------------
extern "C" void kernel_launch(void* const* d_in, const int* in_sizes, int n_in,
                              void* d_out, int out_size) {
    const float* xyz1    = (const float*)d_in[0];
    const float* xyz2    = (const float*)d_in[1];
    const float* points1 = (const float*)d_in[2];
    const float* points2 = (const float*)d_in[3];
    const float* w0  = (const float*)d_in[4];
    const float* b0  = (const float*)d_in[5];
    const float* ga0 = (const float*)d_in[6];
    const float* be0 = (const float*)d_in[7];
    const float* w1  = (const float*)d_in[8];
    const float* b1  = (const float*)d_in[9];
    const float* ga1 = (const float*)d_in[10];
    const float* be1 = (const float*)d_in[11];
    float* out = (float*)d_out;

    init_stats_kernel<<<1, 256>>>();
    transpose_p2_kernel<<<dim3(N2 / 32, C2 / 32, BB), dim3(32, 8)>>>(points2);
    knn_kernel<<<BB * (N1 / 128), 128>>>(xyz1, xyz2);
    interp_kernel<<<BB * (N1 / 32), 256>>>();
    conv_kernel<0><<<dim3(BB * (N1 / 128), O1 / 128), 256>>>(points1, w0, b0);
    bn_finalize_kernel<0><<<1, 256>>>(ga0, be0);
    conv_kernel<1><<<dim3(BB * (N1 / 128), O2 / 128), 256>>>(nullptr, w1, b1);
    bn_finalize_kernel<1><<<1, 128>>>(ga1, be1);
    final_kernel<<<(BB * O2 * N1 / 4) / 256, 256>>>(out);
}

// round 4
// speedup vs baseline: 1.8753x; 1.7478x over previous
#include <cuda_runtime.h>
#include <cuda_bf16.h>
#include <math.h>
#include <stdint.h>

#define BB 8
#define N1 8192
#define N2 2048
#define C1 128
#define C2 256
#define KIN1 384
#define O1 256
#define O2 128
#define BN_EPS 1e-5f
#define MIN_DIST 1e-10f
#define P_TOTAL (BB * N1)

// ---------------- scratch (no allocations allowed) ----------------
__device__ float g_p2T[BB * N2 * C2];                 // points2 transposed [B][N2][C2]
__device__ int   g_knn_idx[BB * N1 * 3];
__device__ float g_knn_w[BB * N1 * 3];
__device__ __nv_bfloat16 g_w0h[O1 * KIN1], g_w0l[O1 * KIN1];
__device__ __nv_bfloat16 g_w1h[O2 * O1],   g_w1l[O2 * O1];
__device__ __nv_bfloat16 g_x0h[BB * N1 * KIN1], g_x0l[BB * N1 * KIN1];  // conv0 B operand [n][k]
__device__ __nv_bfloat16 g_x2h[BB * N1 * O1],   g_x2l[BB * N1 * O1];    // conv1 B operand [n][k]
__device__ float g_y1T[BB * N1 * O1];                 // conv0 out, point-major [n][o]
__device__ float g_y2[BB * O2 * N1];                  // conv1 out, channel-major [o][n]
__device__ float g_sum0[O1], g_sq0[O1], g_sum1[O2], g_sq1[O2];
__device__ float g_scale0[O1], g_shift0[O1], g_scale1[O2], g_shift1[O2];

// ---------------- helpers ----------------
__device__ __forceinline__ uint32_t smem_u32(const void* p) {
    return (uint32_t)__cvta_generic_to_shared(p);
}
__device__ __forceinline__ void cp16(uint32_t dst, const void* src) {
    asm volatile("cp.async.ca.shared.global [%0], [%1], 16;" :: "r"(dst), "l"(src));
}
__device__ __forceinline__ void cp_commit() {
    asm volatile("cp.async.commit_group;" ::: "memory");
}
template <int N>
__device__ __forceinline__ void cp_wait() {
    asm volatile("cp.async.wait_group %0;" :: "n"(N) : "memory");
}
__device__ __forceinline__ void ldmx4(uint32_t a, uint32_t& r0, uint32_t& r1,
                                      uint32_t& r2, uint32_t& r3) {
    asm volatile("ldmatrix.sync.aligned.m8n8.x4.shared.b16 {%0,%1,%2,%3}, [%4];"
                 : "=r"(r0), "=r"(r1), "=r"(r2), "=r"(r3) : "r"(a));
}
__device__ __forceinline__ void mma16816(float* c, const uint32_t* a,
                                         uint32_t b0, uint32_t b1) {
    asm volatile("mma.sync.aligned.m16n8k16.row.col.f32.bf16.bf16.f32 "
                 "{%0,%1,%2,%3},{%4,%5,%6,%7},{%8,%9},{%0,%1,%2,%3};"
                 : "+f"(c[0]), "+f"(c[1]), "+f"(c[2]), "+f"(c[3])
                 : "r"(a[0]), "r"(a[1]), "r"(a[2]), "r"(a[3]), "r"(b0), "r"(b1));
}
__device__ __forceinline__ void split_bf16(float v, __nv_bfloat16& h, __nv_bfloat16& l) {
    h = __float2bfloat16(v);
    l = __float2bfloat16(v - __bfloat162float(h));
}

// ---------------- stats zero (graph replays!) ----------------
__global__ void init_stats_kernel() {
    int t = threadIdx.x;
    if (t < O1) { g_sum0[t] = 0.f; g_sq0[t] = 0.f; }
    if (t < O2) { g_sum1[t] = 0.f; g_sq1[t] = 0.f; }
}

// ---------------- weight split fp32 -> bf16 hi/lo ----------------
__global__ void split_w_kernel(const float* __restrict__ src,
                               __nv_bfloat16* __restrict__ dh,
                               __nv_bfloat16* __restrict__ dl, int n) {
    int i = blockIdx.x * blockDim.x + threadIdx.x;
    if (i < n) { __nv_bfloat16 h, l; split_bf16(src[i], h, l); dh[i] = h; dl[i] = l; }
}

// ---------------- transpose points2 [B,C2,N2] -> [B,N2,C2] ----------------
__global__ void transpose_p2_kernel(const float* __restrict__ p2) {
    __shared__ float tile[32][33];
    int b = blockIdx.z, c0 = blockIdx.y * 32, n0 = blockIdx.x * 32;
    int tx = threadIdx.x, ty = threadIdx.y;
    #pragma unroll
    for (int i = ty; i < 32; i += 8)
        tile[i][tx] = p2[(size_t)b * C2 * N2 + (size_t)(c0 + i) * N2 + n0 + tx];
    __syncthreads();
    #pragma unroll
    for (int i = ty; i < 32; i += 8)
        g_p2T[(size_t)b * N2 * C2 + (size_t)(n0 + i) * C2 + c0 + tx] = tile[tx][i];
}

// ---------------- transpose+split points1 [B,C1,N1] -> x0 [n][0..127] ----------------
__global__ void transpose_p1_kernel(const float* __restrict__ p1) {
    __shared__ float tile[32][33];
    int b = blockIdx.z, c0 = blockIdx.y * 32, n0 = blockIdx.x * 32;
    int tx = threadIdx.x, ty = threadIdx.y;
    #pragma unroll
    for (int i = ty; i < 32; i += 8)
        tile[i][tx] = p1[(size_t)b * C1 * N1 + (size_t)(c0 + i) * N1 + n0 + tx];
    __syncthreads();
    #pragma unroll
    for (int i = ty; i < 32; i += 8) {
        __nv_bfloat16 h, l; split_bf16(tile[tx][i], h, l);
        size_t idx = ((size_t)b * N1 + n0 + i) * KIN1 + c0 + tx;
        g_x0h[idx] = h; g_x0l[idx] = l;
    }
}

// ---------------- 3-NN ----------------
__global__ __launch_bounds__(128) void knn_kernel(const float* __restrict__ xyz1,
                                                  const float* __restrict__ xyz2) {
    __shared__ float4 s_p[N2];
    int b  = blockIdx.x >> 6;
    int n0 = (blockIdx.x & 63) << 7;
    const float* x2 = xyz2 + (size_t)b * N2 * 3;
    for (int j = threadIdx.x; j < N2; j += 128) {
        float px = x2[j * 3], py = x2[j * 3 + 1], pz = x2[j * 3 + 2];
        s_p[j] = make_float4(px, py, pz, px * px + py * py + pz * pz);
    }
    __syncthreads();
    int n = n0 + threadIdx.x;
    const float* q = xyz1 + ((size_t)b * N1 + n) * 3;
    float qx = q[0], qy = q[1], qz = q[2];
    float qn = qx * qx + qy * qy + qz * qz;
    float d0 = 3.4e38f, d1 = 3.4e38f, d2 = 3.4e38f;
    int   i0 = 0, i1 = 0, i2 = 0;
    #pragma unroll 4
    for (int j = 0; j < N2; j++) {
        float4 p = s_p[j];
        float t  = fmaf(qx, p.x, fmaf(qy, p.y, qz * p.z));
        float sq = qn + p.w - 2.f * t;
        if (sq < d2) {
            if (sq < d1) {
                d2 = d1; i2 = i1;
                if (sq < d0) { d1 = d0; i1 = i0; d0 = sq; i0 = j; }
                else         { d1 = sq; i1 = j; }
            } else { d2 = sq; i2 = j; }
        }
    }
    float e0 = fmaxf(sqrtf(fmaxf(d0, 0.f)), MIN_DIST);
    float e1 = fmaxf(sqrtf(fmaxf(d1, 0.f)), MIN_DIST);
    float e2 = fmaxf(sqrtf(fmaxf(d2, 0.f)), MIN_DIST);
    float w0 = 1.f / e0, w1 = 1.f / e1, w2 = 1.f / e2;
    float inv = 1.f / (w0 + w1 + w2);
    size_t on = ((size_t)b * N1 + n) * 3;
    g_knn_idx[on] = i0; g_knn_idx[on + 1] = i1; g_knn_idx[on + 2] = i2;
    g_knn_w[on] = w0 * inv; g_knn_w[on + 1] = w1 * inv; g_knn_w[on + 2] = w2 * inv;
}

// ---------------- interpolation -> x0 [n][128..383] bf16 split ----------------
__global__ __launch_bounds__(256) void interp_kernel() {
    __shared__ int   s_idx[96];
    __shared__ float s_w[96];
    int b  = blockIdx.x >> 8;
    int n0 = (blockIdx.x & 255) << 5;
    int t  = threadIdx.x;
    if (t < 96) {
        size_t base = ((size_t)b * N1 + n0) * 3 + t;
        s_idx[t] = g_knn_idx[base];
        s_w[t]   = g_knn_w[base];
    }
    __syncthreads();
    int c = t;
    #pragma unroll 4
    for (int p = 0; p < 32; p++) {
        int k = p * 3;
        const float* r0 = g_p2T + ((size_t)b * N2 + s_idx[k + 0]) * C2 + c;
        const float* r1 = g_p2T + ((size_t)b * N2 + s_idx[k + 1]) * C2 + c;
        const float* r2 = g_p2T + ((size_t)b * N2 + s_idx[k + 2]) * C2 + c;
        float v = fmaf(s_w[k], *r0, fmaf(s_w[k + 1], *r1, s_w[k + 2] * (*r2)));
        __nv_bfloat16 h, l; split_bf16(v, h, l);
        size_t idx = ((size_t)b * N1 + n0 + p) * KIN1 + C1 + c;
        g_x0h[idx] = h; g_x0l[idx] = l;
    }
}

// ---------------- mma.sync conv: D[o][n] = sum_k W[o][k] X[n][k], bf16 split x3 ----------------
// CTA 128x128, 8 warps (2x4 -> 64x32 each), K-chunk 64, cp.async double buffer.
// SMEM rows padded to 72 bf16 (144 B) -> conflict-free ldmatrix.
#define SM_A0 0
#define SM_A1 18432
#define SM_B0 36864
#define SM_B1 55296
#define SMEM_MMA 73728

template <int LAYER>
__global__ void __launch_bounds__(256, 1) conv_mma_kernel(const float* __restrict__ bias) {
    constexpr int K   = (LAYER == 0) ? KIN1 : O1;
    constexpr int NCH = K / 64;
    constexpr int TOT = 3 * NCH;
    extern __shared__ char smem[];
    uint32_t sb = smem_u32(smem);

    int tid  = threadIdx.x;
    int lane = tid & 31, wid = tid >> 5;
    int m_off = (wid >> 2) * 64;     // warp m-origin (o)
    int n_off = (wid & 3) * 32;      // warp n-origin (points)
    int b  = blockIdx.x >> 6;
    int n0 = (blockIdx.x & 63) << 7;
    int o0 = blockIdx.y << 7;

    const __nv_bfloat16* Wh = (LAYER == 0) ? g_w0h : g_w1h;
    const __nv_bfloat16* Wl = (LAYER == 0) ? g_w0l : g_w1l;
    const __nv_bfloat16* Xh = (LAYER == 0) ? g_x0h : g_x2h;
    const __nv_bfloat16* Xl = (LAYER == 0) ? g_x0l : g_x2l;
    const __nv_bfloat16* Xbase_h = Xh + ((size_t)b * N1 + n0) * K;
    const __nv_bfloat16* Xbase_l = Xl + ((size_t)b * N1 + n0) * K;
    const __nv_bfloat16* Wbase_h = Wh + (size_t)o0 * K;
    const __nv_bfloat16* Wbase_l = Wl + (size_t)o0 * K;

    // ldmatrix per-lane byte offset within a tile-origin: row-in-16 + k-half select
    uint32_t lm_off = (uint32_t)(((lane & 7) + ((lane >> 3) & 1) * 8) * 144 + (lane >> 4) * 16);

    float acc[4][4][4];
    #pragma unroll
    for (int mi = 0; mi < 4; mi++)
        #pragma unroll
        for (int ni = 0; ni < 4; ni++)
            #pragma unroll
            for (int r = 0; r < 4; r++) acc[mi][ni][r] = 0.f;

    int ld_row = tid >> 3;           // for cp.async: rows covered (i*256+tid)>>3
    int ld_seg = tid & 7;

    auto issue_chunk = [&](int c, int buf) {
        int p = c / NCH, j = c - p * NCH;
        int kk = j * 64;
        const __nv_bfloat16* Asrc = ((p == 2) ? Wbase_l : Wbase_h) + kk;
        const __nv_bfloat16* Bsrc = ((p == 1) ? Xbase_l : Xbase_h) + kk;
        uint32_t A = sb + (buf ? SM_A1 : SM_A0);
        uint32_t Bf = sb + (buf ? SM_B1 : SM_B0);
        #pragma unroll
        for (int i = 0; i < 4; i++) {
            int row = ld_row + i * 32;
            uint32_t d = (uint32_t)(row * 144 + ld_seg * 16);
            cp16(A + d,  Asrc + (size_t)row * K + ld_seg * 8);
            cp16(Bf + d, Bsrc + (size_t)row * K + ld_seg * 8);
        }
        cp_commit();
    };

    issue_chunk(0, 0);
    for (int c = 0; c < TOT; c++) {
        int buf = c & 1;
        if (c + 1 < TOT) { issue_chunk(c + 1, buf ^ 1); cp_wait<1>(); }
        else             { cp_wait<0>(); }
        __syncthreads();

        uint32_t A = sb + (buf ? SM_A1 : SM_A0) + (uint32_t)(m_off * 144) + lm_off;
        uint32_t Bf = sb + (buf ? SM_B1 : SM_B0) + (uint32_t)(n_off * 144) + lm_off;
        #pragma unroll
        for (int kst = 0; kst < 4; kst++) {
            uint32_t af[4][4], bf[2][4];
            #pragma unroll
            for (int mi = 0; mi < 4; mi++)
                ldmx4(A + (uint32_t)(mi * 16 * 144 + kst * 32),
                      af[mi][0], af[mi][1], af[mi][2], af[mi][3]);
            #pragma unroll
            for (int nj = 0; nj < 2; nj++)
                ldmx4(Bf + (uint32_t)(nj * 16 * 144 + kst * 32),
                      bf[nj][0], bf[nj][1], bf[nj][2], bf[nj][3]);
            #pragma unroll
            for (int mi = 0; mi < 4; mi++)
                #pragma unroll
                for (int ni = 0; ni < 4; ni++)
                    mma16816(acc[mi][ni], af[mi],
                             bf[ni >> 1][ni & 1], bf[ni >> 1][(ni & 1) + 2]);
        }
        __syncthreads();
    }

    // ---- epilogue: stage D to SMEM [o][n] stride 129, then stats + stores ----
    float* sD = (float*)smem;
    #pragma unroll
    for (int mi = 0; mi < 4; mi++) {
        int r0 = m_off + mi * 16 + (lane >> 2);
        #pragma unroll
        for (int ni = 0; ni < 4; ni++) {
            int cc = n_off + ni * 8 + (lane & 3) * 2;
            sD[r0 * 129 + cc]           = acc[mi][ni][0];
            sD[r0 * 129 + cc + 1]       = acc[mi][ni][1];
            sD[(r0 + 8) * 129 + cc]     = acc[mi][ni][2];
            sD[(r0 + 8) * 129 + cc + 1] = acc[mi][ni][3];
        }
    }
    __syncthreads();

    // stats: 2 threads per output channel (n halves), bias included
    {
        int o = tid & 127;
        int nlo = (tid >> 7) * 64;
        float bi = bias[o0 + o];
        float s = 0.f, s2 = 0.f;
        #pragma unroll 4
        for (int n = nlo; n < nlo + 64; n++) {
            float v = sD[o * 129 + n] + bi;
            s += v;
            s2 = fmaf(v, v, s2);
        }
        float* gs = (LAYER == 0) ? g_sum0 : g_sum1;
        float* gq = (LAYER == 0) ? g_sq0  : g_sq1;
        atomicAdd(&gs[o0 + o], s);
        atomicAdd(&gq[o0 + o], s2);
    }

    // stores
    if (LAYER == 0) {
        for (int e = tid; e < 128 * 128; e += 256) {
            int n = e >> 7, o = e & 127;
            g_y1T[((size_t)b * N1 + n0 + n) * O1 + o0 + o] = sD[o * 129 + n] + bias[o0 + o];
        }
    } else {
        for (int e = tid; e < 128 * 128; e += 256) {
            int o = e >> 7, n = e & 127;
            g_y2[((size_t)b * O2 + o) * N1 + n0 + n] = sD[o * 129 + n] + bias[o];
        }
    }
}

// ---------------- BN finalize ----------------
template <int LAYER>
__global__ void bn_finalize_kernel(const float* __restrict__ gamma,
                                   const float* __restrict__ beta) {
    constexpr int O = (LAYER == 0) ? O1 : O2;
    int o = threadIdx.x;
    if (o < O) {
        const float inv = 1.0f / (float)P_TOTAL;
        float su = (LAYER == 0) ? g_sum0[o] : g_sum1[o];
        float sq = (LAYER == 0) ? g_sq0[o]  : g_sq1[o];
        float mu  = su * inv;
        float var = sq * inv - mu * mu;
        float sc  = gamma[o] * rsqrtf(var + BN_EPS);
        if (LAYER == 0) { g_scale0[o] = sc; g_shift0[o] = beta[o] - mu * sc; }
        else            { g_scale1[o] = sc; g_shift1[o] = beta[o] - mu * sc; }
    }
}

// ---------------- midpass: y1T -> BN0+ReLU -> bf16 split x2 ----------------
__global__ __launch_bounds__(256) void midpass_kernel() {
    size_t i4 = (size_t)blockIdx.x * 256 + threadIdx.x;   // float4 index
    float4 v = ((const float4*)g_y1T)[i4];
    int c0 = (int)((i4 * 4) & (O1 - 1));
    float r[4] = {v.x, v.y, v.z, v.w};
    unsigned short hh[4], ll[4];
    #pragma unroll
    for (int j = 0; j < 4; j++) {
        float x = fmaxf(fmaf(r[j], g_scale0[c0 + j], g_shift0[c0 + j]), 0.f);
        __nv_bfloat16 h, l; split_bf16(x, h, l);
        hh[j] = __bfloat16_as_ushort(h);
        ll[j] = __bfloat16_as_ushort(l);
    }
    uint2 ph = make_uint2((uint32_t)hh[0] | ((uint32_t)hh[1] << 16),
                          (uint32_t)hh[2] | ((uint32_t)hh[3] << 16));
    uint2 pl = make_uint2((uint32_t)ll[0] | ((uint32_t)ll[1] << 16),
                          (uint32_t)ll[2] | ((uint32_t)ll[3] << 16));
    ((uint2*)g_x2h)[i4] = ph;
    ((uint2*)g_x2l)[i4] = pl;
}

// ---------------- final BN1 + ReLU -> output ----------------
__global__ __launch_bounds__(256) void final_kernel(float* __restrict__ out) {
    int i = blockIdx.x * blockDim.x + threadIdx.x;
    float4 v = ((const float4*)g_y2)[i];
    int c = ((i * 4) / N1) & (O2 - 1);
    float sc = g_scale1[c], sh = g_shift1[c];
    v.x = fmaxf(fmaf(v.x, sc, sh), 0.f);
    v.y = fmaxf(fmaf(v.y, sc, sh), 0.f);
    v.z = fmaxf(fmaf(v.z, sc, sh), 0.f);
    v.w = fmaxf(fmaf(v.w, sc, sh), 0.f);
    ((float4*)out)[i] = v;
}

// ---------------- launch ----------------
extern "C" void kernel_launch(void* const* d_in, const int* in_sizes, int n_in,
                              void* d_out, int out_size) {
    const float* xyz1    = (const float*)d_in[0];
    const float* xyz2    = (const float*)d_in[1];
    const float* points1 = (const float*)d_in[2];
    const float* points2 = (const float*)d_in[3];
    const float* w0  = (const float*)d_in[4];
    const float* b0  = (const float*)d_in[5];
    const float* ga0 = (const float*)d_in[6];
    const float* be0 = (const float*)d_in[7];
    const float* w1  = (const float*)d_in[8];
    const float* b1  = (const float*)d_in[9];
    const float* ga1 = (const float*)d_in[10];
    const float* be1 = (const float*)d_in[11];
    float* out = (float*)d_out;

    cudaFuncSetAttribute(conv_mma_kernel<0>, cudaFuncAttributeMaxDynamicSharedMemorySize, SMEM_MMA);
    cudaFuncSetAttribute(conv_mma_kernel<1>, cudaFuncAttributeMaxDynamicSharedMemorySize, SMEM_MMA);

    __nv_bfloat16 *w0h, *w0l, *w1h, *w1l;
    cudaGetSymbolAddress((void**)&w0h, g_w0h);
    cudaGetSymbolAddress((void**)&w0l, g_w0l);
    cudaGetSymbolAddress((void**)&w1h, g_w1h);
    cudaGetSymbolAddress((void**)&w1l, g_w1l);

    init_stats_kernel<<<1, 256>>>();
    split_w_kernel<<<(O1 * KIN1 + 255) / 256, 256>>>(w0, w0h, w0l, O1 * KIN1);
    split_w_kernel<<<(O2 * O1 + 255) / 256, 256>>>(w1, w1h, w1l, O2 * O1);
    transpose_p2_kernel<<<dim3(N2 / 32, C2 / 32, BB), dim3(32, 8)>>>(points2);
    transpose_p1_kernel<<<dim3(N1 / 32, C1 / 32, BB), dim3(32, 8)>>>(points1);
    knn_kernel<<<BB * (N1 / 128), 128>>>(xyz1, xyz2);
    interp_kernel<<<BB * (N1 / 32), 256>>>();
    conv_mma_kernel<0><<<dim3(BB * (N1 / 128), O1 / 128), 256, SMEM_MMA>>>(b0);
    bn_finalize_kernel<0><<<1, 256>>>(ga0, be0);
    midpass_kernel<<<(BB * N1 * O1 / 4) / 256, 256>>>();
    conv_mma_kernel<1><<<dim3(BB * (N1 / 128), O2 / 128), 256, SMEM_MMA>>>(b1);
    bn_finalize_kernel<1><<<1, 128>>>(ga1, be1);
    final_kernel<<<(BB * O2 * N1 / 4) / 256, 256>>>(out);
}